// round 3
// baseline (speedup 1.0000x reference)
#include <cuda_runtime.h>
#include <math.h>

#define KMIX 32
#define DDIM 32
#define MSTRIDE 576   // padded-triangular floats per mixture: sum_i 4*((i>>2)+1)

// Precomputed per-mixture data (scratch: __device__ globals, no allocation)
__device__ float g_M[KMIX * MSTRIDE];  // packed lower-triangular L^{-1}, rows padded to mult of 4
__device__ float g_t[KMIX * DDIM];     // t_k = M_k * mu_k
__device__ float g_c[KMIX];            // c_k = -log(phi) + 0.5*(D*log(2pi) + logdet)

__host__ __device__ constexpr int rowoff(int i) {
    int g = i >> 2, r = i & 3;
    return 8 * g * (g + 1) + r * 4 * (g + 1);
}

// One block (32 threads = 1 warp) per mixture.
__global__ void gmm_precompute(const float* __restrict__ sigmas,
                               const float* __restrict__ mus,
                               const float* __restrict__ phis) {
    __shared__ float L[DDIM][DDIM];
    __shared__ float Mi[DDIM][DDIM];
    int k = blockIdx.x;
    int lane = threadIdx.x;

    for (int idx = lane; idx < DDIM * DDIM; idx += 32) {
        L[idx >> 5][idx & 31] = sigmas[k * DDIM * DDIM + idx];
        Mi[idx >> 5][idx & 31] = 0.0f;
    }
    __syncwarp();

    // In-place Cholesky (lower) of sigma_k.
    for (int j = 0; j < DDIM; j++) {
        float s = 0.0f;
        if (lane >= j) {
            s = L[lane][j];
            for (int p = 0; p < j; p++) s -= L[lane][p] * L[j][p];
        }
        __syncwarp();
        if (lane == j) L[j][j] = sqrtf(s);
        __syncwarp();
        if (lane > j) L[lane][j] = s / L[j][j];
        __syncwarp();
    }

    // Mi = L^{-1} (lower triangular). Lane c solves column c.
    {
        int c = lane;
        for (int i = c; i < DDIM; i++) {
            float s = (i == c) ? 1.0f : 0.0f;
            for (int p = c; p < i; p++) s -= L[i][p] * Mi[p][c];
            Mi[i][c] = s / L[i][i];
        }
    }
    __syncwarp();

    // Write packed-triangular M (rows padded to multiple of 4; pad entries are 0).
    for (int i = 0; i < DDIM; i++) {
        int len = 4 * ((i >> 2) + 1);
        for (int j = lane; j < len; j += 32)
            g_M[k * MSTRIDE + rowoff(i) + j] = Mi[i][j];
    }

    // t_k = Mi * mu_k  (lane i computes t_i)
    {
        float tv = 0.0f;
        for (int j = 0; j <= lane; j++) tv += Mi[lane][j] * mus[k * DDIM + j];
        g_t[k * DDIM + lane] = tv;
    }

    if (lane == 0) {
        float logdet = 0.0f;
        for (int j = 0; j < DDIM; j++) logdet += logf(L[j][j]);
        logdet *= 2.0f;
        const float log2pi = 1.8378770664093453f; // log(2*pi)
        g_c[k] = -logf(phis[k]) + 0.5f * ((float)DDIM * log2pi + logdet);
    }
}

__global__ void __launch_bounds__(256, 2)
gmm_main(const float* __restrict__ X, float* __restrict__ out, int N) {
    extern __shared__ float sh[];
    float* sM = sh;                          // KMIX*MSTRIDE
    float* sT = sh + KMIX * MSTRIDE;         // KMIX*DDIM
    float* sC = sT + KMIX * DDIM;            // KMIX

    int tid = threadIdx.x;
    for (int i = tid; i < KMIX * MSTRIDE; i += 256) sM[i] = g_M[i];
    for (int i = tid; i < KMIX * DDIM;    i += 256) sT[i] = g_t[i];
    if (tid < KMIX) sC[tid] = g_c[tid];
    __syncthreads();

    int n = blockIdx.x * 256 + tid;
    if (n >= N) return;

    float x[DDIM];
    {
        const float4* xp = reinterpret_cast<const float4*>(X + (size_t)n * DDIM);
#pragma unroll
        for (int j = 0; j < 8; j++) {
            float4 v = xp[j];
            x[4 * j + 0] = v.x; x[4 * j + 1] = v.y;
            x[4 * j + 2] = v.z; x[4 * j + 3] = v.w;
        }
    }

    float val[KMIX];
    float vmax = -1e30f;
    for (int k = 0; k < KMIX; k++) {
        const float4* Mk = reinterpret_cast<const float4*>(sM + k * MSTRIDE);
        const float*  tk = sT + k * DDIM;
        float q = 0.0f;
#pragma unroll
        for (int i = 0; i < DDIM; i++) {
            const int nvec = (i >> 2) + 1;
            const int base = rowoff(i) >> 2;
            float acc = -tk[i];
#pragma unroll
            for (int v4 = 0; v4 < nvec; v4++) {
                float4 m = Mk[base + v4];
                acc = fmaf(m.x, x[4 * v4 + 0], acc);
                acc = fmaf(m.y, x[4 * v4 + 1], acc);
                acc = fmaf(m.z, x[4 * v4 + 2], acc);
                acc = fmaf(m.w, x[4 * v4 + 3], acc);
            }
            q = fmaf(acc, acc, q);
        }
        float v = fmaf(0.5f, q, sC[k]);
        val[k] = v;
        vmax = fmaxf(vmax, v);
    }

    float inv = 1.0f / vmax;
    float4* op = reinterpret_cast<float4*>(out + (size_t)n * DDIM);
#pragma unroll
    for (int j = 0; j < 8; j++) {
        float4 o;
        o.x = val[4 * j + 0] * inv; o.y = val[4 * j + 1] * inv;
        o.z = val[4 * j + 2] * inv; o.w = val[4 * j + 3] * inv;
        op[j] = o;
    }
}

extern "C" void kernel_launch(void* const* d_in, const int* in_sizes, int n_in,
                              void* d_out, int out_size) {
    const float* X      = (const float*)d_in[0];
    const float* mus    = (const float*)d_in[1];
    const float* sigmas = (const float*)d_in[2];
    const float* phis   = (const float*)d_in[3];
    float* out = (float*)d_out;

    int N = in_sizes[0] / DDIM;

    gmm_precompute<<<KMIX, 32>>>(sigmas, mus, phis);

    size_t shmem = (KMIX * MSTRIDE + KMIX * DDIM + KMIX) * sizeof(float);
    cudaFuncSetAttribute((const void*)gmm_main,
                         cudaFuncAttributeMaxDynamicSharedMemorySize, (int)shmem);
    int blocks = (N + 255) / 256;
    gmm_main<<<blocks, 256, shmem>>>(X, out, N);
}

// round 5
// speedup vs baseline: 1.3475x; 1.3475x over previous
#include <cuda_runtime.h>
#include <math.h>

#define KMIX 32
#define DDIM 32
#define MSTRIDE 576   // padded-triangular floats per mixture: sum_i 4*((i>>2)+1)

__device__ float g_M[KMIX * MSTRIDE];  // packed lower-triangular L^{-1}, rows padded to mult of 4
__device__ float g_t[KMIX * DDIM];     // t_k = M_k * mu_k
__device__ float g_c[KMIX];            // c_k = -log(phi) + 0.5*(D*log(2pi) + logdet)

__host__ __device__ constexpr int rowoff(int i) {
    int g = i >> 2, r = i & 3;
    return 8 * g * (g + 1) + r * 4 * (g + 1);
}

// ---------------- precompute: one warp per mixture ----------------
__global__ void gmm_precompute(const float* __restrict__ sigmas,
                               const float* __restrict__ mus,
                               const float* __restrict__ phis) {
    __shared__ float L[DDIM][DDIM];
    __shared__ float Mi[DDIM][DDIM];
    int k = blockIdx.x;
    int lane = threadIdx.x;

    for (int idx = lane; idx < DDIM * DDIM; idx += 32) {
        L[idx >> 5][idx & 31] = sigmas[k * DDIM * DDIM + idx];
        Mi[idx >> 5][idx & 31] = 0.0f;
    }
    __syncwarp();

    for (int j = 0; j < DDIM; j++) {
        float s = 0.0f;
        if (lane >= j) {
            s = L[lane][j];
            for (int p = 0; p < j; p++) s -= L[lane][p] * L[j][p];
        }
        __syncwarp();
        if (lane == j) L[j][j] = sqrtf(s);
        __syncwarp();
        if (lane > j) L[lane][j] = s / L[j][j];
        __syncwarp();
    }

    { // Mi = L^{-1}, lane c solves column c
        int c = lane;
        for (int i = c; i < DDIM; i++) {
            float s = (i == c) ? 1.0f : 0.0f;
            for (int p = c; p < i; p++) s -= L[i][p] * Mi[p][c];
            Mi[i][c] = s / L[i][i];
        }
    }
    __syncwarp();

    for (int i = 0; i < DDIM; i++) {
        int len = 4 * ((i >> 2) + 1);
        for (int j = lane; j < len; j += 32)
            g_M[k * MSTRIDE + rowoff(i) + j] = Mi[i][j];
    }

    {
        float tv = 0.0f;
        for (int j = 0; j <= lane; j++) tv += Mi[lane][j] * mus[k * DDIM + j];
        g_t[k * DDIM + lane] = tv;
    }

    if (lane == 0) {
        float logdet = 0.0f;
        for (int j = 0; j < DDIM; j++) logdet += logf(L[j][j]);
        logdet *= 2.0f;
        const float log2pi = 1.8378770664093453f;
        g_c[k] = -logf(phis[k]) + 0.5f * ((float)DDIM * log2pi + logdet);
    }
}

// ---------------- main ----------------
__device__ __forceinline__ unsigned long long fma2(unsigned long long a,
                                                   unsigned long long b,
                                                   unsigned long long c) {
    unsigned long long d;
    asm("fma.rn.f32x2 %0, %1, %2, %3;" : "=l"(d) : "l"(a), "l"(b), "l"(c));
    return d;
}
__device__ __forceinline__ float hadd2(unsigned long long a) {
    float lo, hi;
    asm("mov.b64 {%0, %1}, %2;" : "=f"(lo), "=f"(hi) : "l"(a));
    return lo + hi;
}
__device__ __forceinline__ unsigned long long pack2(float lo, float hi) {
    unsigned long long d;
    asm("mov.b64 %0, {%1, %2};" : "=l"(d) : "f"(lo), "f"(hi));
    return d;
}

#define BLK 256
#define SPT 2   // samples per thread

// smem float layout: M [0,18432) | t [18432,19456) | c [19456,19488) | scratch (ull)
#define SM_T 18432
#define SM_C 19456
#define SM_SCR 19488   // float index; 8/16-byte aligned

__global__ void __launch_bounds__(BLK, 1)
gmm_main(const float* __restrict__ X, float* __restrict__ out, int N) {
    extern __shared__ float sh[];
    float* sM = sh;
    float* sT = sh + SM_T;
    float* sC = sh + SM_C;
    unsigned long long* sScr = reinterpret_cast<unsigned long long*>(sh + SM_SCR);

    int tid = threadIdx.x;
    {   // fill smem (float4 copies)
        const float4* gm4 = reinterpret_cast<const float4*>(g_M);
        float4* sm4 = reinterpret_cast<float4*>(sM);
        for (int i = tid; i < (KMIX * MSTRIDE) / 4; i += BLK) sm4[i] = gm4[i];
        const float4* gt4 = reinterpret_cast<const float4*>(g_t);
        float4* st4 = reinterpret_cast<float4*>(sT);
        for (int i = tid; i < (KMIX * DDIM) / 4; i += BLK) st4[i] = gt4[i];
        if (tid < KMIX) sC[tid] = g_c[tid];
    }
    __syncthreads();

    int base0 = blockIdx.x * (BLK * SPT) + tid;
    int base1 = base0 + BLK;
    if (base0 >= N) return;
    bool ok1 = (base1 < N);

    // load X rows as natural j-pairs (16 x b64 per sample, zero packing cost)
    unsigned long long x0[16], x1[16];
    {
        const ulonglong2* xp = reinterpret_cast<const ulonglong2*>(X + (size_t)base0 * DDIM);
#pragma unroll
        for (int j = 0; j < 8; j++) { ulonglong2 v = xp[j]; x0[2 * j] = v.x; x0[2 * j + 1] = v.y; }
        const ulonglong2* xq = reinterpret_cast<const ulonglong2*>(X + (size_t)(ok1 ? base1 : base0) * DDIM);
#pragma unroll
        for (int j = 0; j < 8; j++) { ulonglong2 v = xq[j]; x1[2 * j] = v.x; x1[2 * j + 1] = v.y; }
    }

    float vmax0 = -3.0e38f, vmax1 = -3.0e38f;

#pragma unroll 1
    for (int k = 0; k < KMIX; k++) {
        const float* Mk = sM + k * MSTRIDE;
        const float4* tk4 = reinterpret_cast<const float4*>(sT + k * DDIM);
        float q0 = 0.0f, q1 = 0.0f;
#pragma unroll
        for (int g = 0; g < 8; g++) {
            float4 t4 = tk4[g];
#pragma unroll
            for (int r = 0; r < 4; r++) {
                const int i = 4 * g + r;
                const ulonglong2* row = reinterpret_cast<const ulonglong2*>(Mk + rowoff(i));
                unsigned long long a0 = 0ull, a1 = 0ull;
#pragma unroll
                for (int v = 0; v < (g + 1); v++) {
                    ulonglong2 m = row[v];               // 4 floats: j..j+3 (pads are 0)
                    a0 = fma2(m.x, x0[2 * v], a0);
                    a0 = fma2(m.y, x0[2 * v + 1], a0);
                    a1 = fma2(m.x, x1[2 * v], a1);
                    a1 = fma2(m.y, x1[2 * v + 1], a1);
                }
                float tv = (r == 0) ? t4.x : (r == 1) ? t4.y : (r == 2) ? t4.z : t4.w;
                float y0 = hadd2(a0) - tv;
                float y1 = hadd2(a1) - tv;
                q0 = fmaf(y0, y0, q0);
                q1 = fmaf(y1, y1, q1);
            }
        }
        float c = sC[k];
        float v0 = fmaf(0.5f, q0, c);
        float v1 = fmaf(0.5f, q1, c);
        vmax0 = fmaxf(vmax0, v0);
        vmax1 = fmaxf(vmax1, v1);
        sScr[k * BLK + tid] = pack2(v0, v1);   // own slot; no sync needed
    }

    float inv0 = 1.0f / vmax0;
    float inv1 = 1.0f / vmax1;
    float4* op0 = reinterpret_cast<float4*>(out + (size_t)base0 * DDIM);
    float4* op1 = reinterpret_cast<float4*>(out + (size_t)base1 * DDIM);
#pragma unroll
    for (int jq = 0; jq < 8; jq++) {
        float4 o0, o1;
#pragma unroll
        for (int c = 0; c < 4; c++) {
            unsigned long long v = sScr[(4 * jq + c) * BLK + tid];
            float lo, hi;
            asm("mov.b64 {%0, %1}, %2;" : "=f"(lo), "=f"(hi) : "l"(v));
            float r0 = lo * inv0, r1 = hi * inv1;
            if (c == 0) { o0.x = r0; o1.x = r1; }
            else if (c == 1) { o0.y = r0; o1.y = r1; }
            else if (c == 2) { o0.z = r0; o1.z = r1; }
            else { o0.w = r0; o1.w = r1; }
        }
        op0[jq] = o0;
        if (ok1) op1[jq] = o1;
    }
}

extern "C" void kernel_launch(void* const* d_in, const int* in_sizes, int n_in,
                              void* d_out, int out_size) {
    const float* X      = (const float*)d_in[0];
    const float* mus    = (const float*)d_in[1];
    const float* sigmas = (const float*)d_in[2];
    const float* phis   = (const float*)d_in[3];
    float* out = (float*)d_out;

    int N = in_sizes[0] / DDIM;

    gmm_precompute<<<KMIX, 32>>>(sigmas, mus, phis);

    size_t shmem = (size_t)SM_SCR * sizeof(float) + (size_t)KMIX * BLK * sizeof(unsigned long long);
    cudaFuncSetAttribute((const void*)gmm_main,
                         cudaFuncAttributeMaxDynamicSharedMemorySize, (int)shmem);
    int blocks = (N + BLK * SPT - 1) / (BLK * SPT);
    gmm_main<<<blocks, BLK, shmem>>>(X, out, N);
}